// round 15
// baseline (speedup 1.0000x reference)
#include <cuda_runtime.h>
#include <cuda_bf16.h>

// KL(target || softmax(scores)), target = softmax(gaussian_pdf(classes; mu=label, std=1))
// kl_row = ent[L] - invS_L*(sum_c s_c + sum_{|k|<=8} w[k]*s_{L+k}) + logsumexp(s_row)
// w[k] = expm1(pdf(k)); |k|>8 terms ~5e-15 (machine-exact truncation).
//
// R15: R14 with ONE change: occupancy 6 -> 8 blocks/SM (__launch_bounds__
// (256,8) forces 32 regs) and grid 1184 = 148 x 8 to fill the wider wave.
// Rationale: every profile shows nothing saturated (latency-bound); resident
// warp count is the lever that has consistently moved the needle.

#define C 100
#define GRID_BLOCKS 1184
#define WARPS_PER_BLOCK 8

__device__ float2        g_lut[C];   // (invS_L, ent_L)
__device__ float         g_w[17];    // expm1(pdf(k)), k = i-8
__device__ double        g_acc;
__device__ unsigned int  g_count;
__device__ int           g_is64;

// ---------------------------------------------------------------------------
// Kernel 1: per-label (invS, ent) + w vector; block 0 detects label dtype and
// zeroes accumulators. Grid: C blocks x 32 threads.
// ---------------------------------------------------------------------------
__global__ void prep(const int* __restrict__ labels_raw, int n) {
    const int L = blockIdx.x;
    const int lane = threadIdx.x;  // 0..31
    const float inv_norm = 0.39894228040143267794f;  // 1/sqrt(2*pi)

    if (blockIdx.x == 0) {
        int nz = 0;
        int limit = (n < 128) ? n : 128;
#pragma unroll
        for (int k = 0; k < 4; k++) {
            int i = lane + 32 * k;
            if (i < limit && labels_raw[2 * i + 1] != 0) nz = 1;
        }
        unsigned int ballot = __ballot_sync(0xffffffffu, nz);
        if (lane == 0) {
            g_is64 = (ballot == 0u) ? 1 : 0;
            g_acc = 0.0;
            g_count = 0u;
        }
        if (lane < 17) {
            float k = (float)(lane - 8);
            g_w[lane] = expm1f(inv_norm * expf(-0.5f * k * k));
        }
    }

    float code[4];
    float esum = 0.f;
#pragma unroll
    for (int k = 0; k < 4; k++) {
        int c = lane + 32 * k;
        if (c < C) {
            float dd = (float)(c - L);
            code[k] = inv_norm * expf(-0.5f * dd * dd);
            esum += expf(code[k]);
        } else {
            code[k] = 0.f;
        }
    }
#pragma unroll
    for (int off = 16; off; off >>= 1)
        esum += __shfl_xor_sync(0xffffffffu, esum, off);

    float ls = logf(esum);
    float inv_s = 1.0f / esum;
    float tlt = 0.f;
#pragma unroll
    for (int k = 0; k < 4; k++) {
        int c = lane + 32 * k;
        if (c < C) {
            float t = expf(code[k]) * inv_s;
            tlt += t * (code[k] - ls);  // t * log t
        }
    }
#pragma unroll
    for (int off = 16; off; off >>= 1)
        tlt += __shfl_xor_sync(0xffffffffu, tlt, off);

    if (lane == 0) g_lut[L] = make_float2(inv_s, tlt);
}

// ---------------------------------------------------------------------------
// Kernel 2: persistent streaming pass + fused finalize.
// Each warp strides over 4-row chunks; 8 lanes per row.
// ---------------------------------------------------------------------------
__global__ __launch_bounds__(256, 8) void kl_main(const float* __restrict__ scores,
                                                  const void* __restrict__ labels,
                                                  float* __restrict__ out,
                                                  int n, int nblocks) {
    const int warp = threadIdx.x >> 5;
    const int lane = threadIdx.x & 31;
    const int g    = lane >> 3;        // group (row within chunk)
    const int j    = lane & 7;         // lane within group

    __shared__ float s_partial;
    if (threadIdx.x == 0) s_partial = 0.f;
    __syncthreads();

    const int is64 = g_is64;
    // Window weights: lane j owns window elems i=j, i=j+8, (j==0) i=16.
    const float w0 = g_w[j];
    const float w1 = g_w[j + 8];
    const float w2 = (j == 0) ? g_w[16] : 0.f;

    const int total_warps = gridDim.x * WARPS_PER_BLOCK;
    const int nchunks = (n + 3) >> 2;   // 4-row chunks

    float v = 0.f;  // per-thread contribution to sum(kl)

    int chunk = blockIdx.x * WARPS_PER_BLOCK + warp;

    // incremental row pointer: this warp's row for its first chunk, advanced
    // by a fixed stride each iteration (no per-iteration row*C IMAD chain).
    const size_t chunk_stride = (size_t)total_warps * 4 * C;  // floats
    const float* srow = scores + ((size_t)chunk * 4 + g) * C;

    // --- prefetch labels for first chunk (lanes 0..3) ---
    int lab = 0;
    if (chunk < nchunks && lane < 4) {
        int r = chunk * 4 + lane;
        if (r >= n) r = n - 1;
        lab = is64 ? (int)((const long long*)labels)[r]
                   : ((const int*)labels)[r];
    }

    while (chunk < nchunks) {
        const int next = chunk + total_warps;

        // --- prefetch next chunk's labels early (independent of this chunk) ---
        int nlab = 0;
        if (next < nchunks && lane < 4) {
            int r = next * 4 + lane;
            if (r >= n) r = n - 1;
            nlab = is64 ? (int)((const long long*)labels)[r]
                        : ((const int*)labels)[r];
        }

        // --- LUT for current labels (L1-hot, 800B table) ---
        float2 lut = make_float2(0.f, 0.f);
        if (lane < 4) lut = g_lut[lab];

        const int   L    = __shfl_sync(0xffffffffu, lab,   g);
        const float invS = __shfl_sync(0xffffffffu, lut.x, g);
        const float ent  = __shfl_sync(0xffffffffu, lut.y, g);

        const int row = chunk * 4 + g;
        const bool valid = (row < n);
        const float4* sv = (const float4*)srow;

        // --- streaming loads: 3 float4 per lane (+1 on j==0) ---
        float4 a = make_float4(0.f, 0.f, 0.f, 0.f), b = a, c4 = a, dd = a;
        float s0 = 0.f, s1 = 0.f, s2 = 0.f;
        if (valid) {
            a  = sv[j];
            b  = sv[j + 8];
            c4 = sv[j + 16];
            if (j == 0) dd = sv[24];
            // window reload around L (L1/L2 hit)
            const int c0 = L - 8 + j;
            const int c1 = L + j;
            if (c0 >= 0) s0 = srow[c0];
            if (c1 < C)  s1 = srow[c1];
            if (j == 0 && L + 8 < C) s2 = srow[L + 8];
        }

        float e = 0.f, ps = 0.f;
        if (valid) {
            e  = __expf(a.x) + __expf(a.y) + __expf(a.z) + __expf(a.w)
               + __expf(b.x) + __expf(b.y) + __expf(b.z) + __expf(b.w)
               + __expf(c4.x) + __expf(c4.y) + __expf(c4.z) + __expf(c4.w);
            ps = a.x + a.y + a.z + a.w
               + b.x + b.y + b.z + b.w
               + c4.x + c4.y + c4.z + c4.w;
            if (j == 0) {
                e  += __expf(dd.x) + __expf(dd.y) + __expf(dd.z) + __expf(dd.w);
                ps += dd.x + dd.y + dd.z + dd.w;
            }
        }
        const float pc = w0 * s0 + w1 * s1 + w2 * s2;

        // --- 8-lane group reduce of e (covers all 4 rows at once) ---
        e += __shfl_xor_sync(0xffffffffu, e, 1);
        e += __shfl_xor_sync(0xffffffffu, e, 2);
        e += __shfl_xor_sync(0xffffffffu, e, 4);

        if (valid) {
            v -= invS * (ps + pc);
            if (j == 0) v += ent + __logf(e);
        }

        lab = nlab;
        chunk = next;
        srow += chunk_stride;
    }

    // --- single final per-warp reduce ---
#pragma unroll
    for (int off = 16; off; off >>= 1)
        v += __shfl_xor_sync(0xffffffffu, v, off);

    if (lane == 0)
        atomicAdd(&s_partial, v);
    __syncthreads();

    if (threadIdx.x == 0) {
        atomicAdd(&g_acc, (double)s_partial);
        __threadfence();
        unsigned int done = atomicAdd(&g_count, 1u);
        if (done == (unsigned int)(nblocks - 1)) {
            double total = atomicAdd(&g_acc, 0.0);
            out[0] = (float)(total / (double)n);
        }
    }
}

extern "C" void kernel_launch(void* const* d_in, const int* in_sizes, int n_in,
                              void* d_out, int out_size) {
    const float* scores = (const float*)d_in[0];
    const void*  labels = d_in[1];
    const int n = in_sizes[1];  // number of rows / labels

    prep<<<C, 32>>>((const int*)labels, n);
    kl_main<<<GRID_BLOCKS, 256>>>(scores, labels, (float*)d_out, n, GRID_BLOCKS);
}

// round 17
// speedup vs baseline: 1.2764x; 1.2764x over previous
#include <cuda_runtime.h>
#include <cuda_bf16.h>

// KL(target || softmax(scores)), target = softmax(gaussian_pdf(classes; mu=label, std=1))
// kl_row = ent[L] - invS_L*(sum_c s_c + sum_{|k|<=8} w[k]*s_{L+k}) + logsumexp(s_row)
// w[k] = expm1(pdf(k)); |k|>8 terms ~5e-15 (machine-exact truncation).
//
// R16: R14 base (persistent single-wave grid 888, occ 6, 4-row chunks, label
// prefetch) + packed f32x2 arithmetic (add.rn.f32x2 / mul.rn.f32x2 on the
// register-adjacent halves of LDG.128 results) + all-valid fast path (n%4==0)
// to eliminate per-element predicates. Goal: cut issued instructions/iter.

#define C 100
#define GRID_BLOCKS 888
#define WARPS_PER_BLOCK 8

typedef unsigned long long ull;

__device__ __forceinline__ ull ADD2(ull a, ull b) {
    ull r; asm("add.rn.f32x2 %0, %1, %2;" : "=l"(r) : "l"(a), "l"(b)); return r;
}
__device__ __forceinline__ ull MUL2(ull a, ull b) {
    ull r; asm("mul.rn.f32x2 %0, %1, %2;" : "=l"(r) : "l"(a), "l"(b)); return r;
}
__device__ __forceinline__ float EX2A(float x) {
    float r; asm("ex2.approx.ftz.f32 %0, %1;" : "=f"(r) : "f"(x)); return r;
}
__device__ __forceinline__ void UPK(ull p, float& lo, float& hi) {
    asm("mov.b64 {%0, %1}, %2;" : "=f"(lo), "=f"(hi) : "l"(p));
}
__device__ __forceinline__ ull PK(float lo, float hi) {
    ull r; asm("mov.b64 %0, {%1, %2};" : "=l"(r) : "f"(lo), "f"(hi)); return r;
}

__device__ float2        g_lut[C];   // (invS_L, ent_L)
__device__ float         g_w[17];    // expm1(pdf(k)), k = i-8
__device__ double        g_acc;
__device__ unsigned int  g_count;
__device__ int           g_is64;

// ---------------------------------------------------------------------------
// Kernel 1: per-label (invS, ent) + w vector; block 0 detects label dtype and
// zeroes accumulators. Grid: C blocks x 32 threads.
// ---------------------------------------------------------------------------
__global__ void prep(const int* __restrict__ labels_raw, int n) {
    const int L = blockIdx.x;
    const int lane = threadIdx.x;  // 0..31
    const float inv_norm = 0.39894228040143267794f;  // 1/sqrt(2*pi)

    if (blockIdx.x == 0) {
        int nz = 0;
        int limit = (n < 128) ? n : 128;
#pragma unroll
        for (int k = 0; k < 4; k++) {
            int i = lane + 32 * k;
            if (i < limit && labels_raw[2 * i + 1] != 0) nz = 1;
        }
        unsigned int ballot = __ballot_sync(0xffffffffu, nz);
        if (lane == 0) {
            g_is64 = (ballot == 0u) ? 1 : 0;
            g_acc = 0.0;
            g_count = 0u;
        }
        if (lane < 17) {
            float k = (float)(lane - 8);
            g_w[lane] = expm1f(inv_norm * expf(-0.5f * k * k));
        }
    }

    float code[4];
    float esum = 0.f;
#pragma unroll
    for (int k = 0; k < 4; k++) {
        int c = lane + 32 * k;
        if (c < C) {
            float dd = (float)(c - L);
            code[k] = inv_norm * expf(-0.5f * dd * dd);
            esum += expf(code[k]);
        } else {
            code[k] = 0.f;
        }
    }
#pragma unroll
    for (int off = 16; off; off >>= 1)
        esum += __shfl_xor_sync(0xffffffffu, esum, off);

    float ls = logf(esum);
    float inv_s = 1.0f / esum;
    float tlt = 0.f;
#pragma unroll
    for (int k = 0; k < 4; k++) {
        int c = lane + 32 * k;
        if (c < C) {
            float t = expf(code[k]) * inv_s;
            tlt += t * (code[k] - ls);  // t * log t
        }
    }
#pragma unroll
    for (int off = 16; off; off >>= 1)
        tlt += __shfl_xor_sync(0xffffffffu, tlt, off);

    if (lane == 0) g_lut[L] = make_float2(inv_s, tlt);
}

// ---------------------------------------------------------------------------
// Kernel 2: persistent streaming pass + fused finalize.
// ---------------------------------------------------------------------------
__global__ __launch_bounds__(256, 6) void kl_main(const float* __restrict__ scores,
                                                  const void* __restrict__ labels,
                                                  float* __restrict__ out,
                                                  int n, int nblocks) {
    const int warp = threadIdx.x >> 5;
    const int lane = threadIdx.x & 31;
    const int g    = lane >> 3;        // group (row within chunk)
    const int j    = lane & 7;         // lane within group

    __shared__ float s_partial;
    if (threadIdx.x == 0) s_partial = 0.f;
    __syncthreads();

    const int is64 = g_is64;
    const float w0 = g_w[j];
    const float w1 = g_w[j + 8];
    const float w2 = (j == 0) ? g_w[16] : 0.f;

    const int total_warps = gridDim.x * WARPS_PER_BLOCK;
    const int nchunks = (n + 3) >> 2;

    const ull L2E2 = PK(1.44269504088896f, 1.44269504088896f);

    float v = 0.f;
    int chunk = blockIdx.x * WARPS_PER_BLOCK + warp;

    const size_t chunk_stride = (size_t)total_warps * 4 * C;  // floats
    const float* srow = scores + ((size_t)chunk * 4 + g) * C;

    // --- prefetch labels for first chunk (lanes 0..3) ---
    int lab = 0;
    if (chunk < nchunks && lane < 4) {
        int r = chunk * 4 + lane;
        if (r >= n) r = n - 1;
        lab = is64 ? (int)((const long long*)labels)[r]
                   : ((const int*)labels)[r];
    }

    if ((n & 3) == 0) {
        // ================= fast path: every chunk fully valid ==============
        while (chunk < nchunks) {
            const int next = chunk + total_warps;

            int nlab = 0;
            if (next < nchunks && lane < 4) {
                int r = next * 4 + lane;
                nlab = is64 ? (int)((const long long*)labels)[r]
                            : ((const int*)labels)[r];
            }

            float2 lut = make_float2(0.f, 0.f);
            if (lane < 4) lut = g_lut[lab];

            const int   L    = __shfl_sync(0xffffffffu, lab,   g);
            const float invS = __shfl_sync(0xffffffffu, lut.x, g);
            const float ent  = __shfl_sync(0xffffffffu, lut.y, g);

            const float4* sv = (const float4*)srow;
            float4 a  = sv[j];
            float4 b  = sv[j + 8];
            float4 c4 = sv[j + 16];
            float4 dd = make_float4(0.f, 0.f, 0.f, 0.f);
            if (j == 0) dd = sv[24];

            // window reload around L (L1 hit)
            const int c0 = L - 8 + j;
            const int c1 = L + j;
            float s0 = (c0 >= 0) ? srow[c0] : 0.f;
            float s1 = (c1 < C)  ? srow[c1] : 0.f;
            float s2 = (j == 0 && L + 8 < C) ? srow[L + 8] : 0.f;

            // --- packed pair views of the loaded quads (register-adjacent) ---
            const ull* ap = reinterpret_cast<const ull*>(&a);
            const ull* bp = reinterpret_cast<const ull*>(&b);
            const ull* cp = reinterpret_cast<const ull*>(&c4);
            const ull* dp = reinterpret_cast<const ull*>(&dd);

            // plain sum via packed adds
            ull ps2 = ADD2(ap[0], ap[1]);
            ps2 = ADD2(ps2, bp[0]);
            ps2 = ADD2(ps2, bp[1]);
            ps2 = ADD2(ps2, cp[0]);
            ps2 = ADD2(ps2, cp[1]);
            if (j == 0) {
                ps2 = ADD2(ps2, dp[0]);
                ps2 = ADD2(ps2, dp[1]);
            }
            float pl, ph; UPK(ps2, pl, ph);
            const float ps = pl + ph;

            // exp pre-scale via packed muls, then EX2 per half
            ull m0 = MUL2(ap[0], L2E2), m1 = MUL2(ap[1], L2E2);
            ull m2 = MUL2(bp[0], L2E2), m3 = MUL2(bp[1], L2E2);
            ull m4 = MUL2(cp[0], L2E2), m5 = MUL2(cp[1], L2E2);
            float x0, x1, x2, x3, x4, x5, x6, x7, x8, x9, xa, xb;
            UPK(m0, x0, x1); UPK(m1, x2, x3);
            UPK(m2, x4, x5); UPK(m3, x6, x7);
            UPK(m4, x8, x9); UPK(m5, xa, xb);
            float e = ((EX2A(x0) + EX2A(x1)) + (EX2A(x2) + EX2A(x3)))
                    + ((EX2A(x4) + EX2A(x5)) + (EX2A(x6) + EX2A(x7)))
                    + ((EX2A(x8) + EX2A(x9)) + (EX2A(xa) + EX2A(xb)));
            if (j == 0) {
                ull m6 = MUL2(dp[0], L2E2), m7 = MUL2(dp[1], L2E2);
                float y0, y1, y2, y3;
                UPK(m6, y0, y1); UPK(m7, y2, y3);
                e += (EX2A(y0) + EX2A(y1)) + (EX2A(y2) + EX2A(y3));
            }

            const float pc = w0 * s0 + w1 * s1 + w2 * s2;

            e += __shfl_xor_sync(0xffffffffu, e, 1);
            e += __shfl_xor_sync(0xffffffffu, e, 2);
            e += __shfl_xor_sync(0xffffffffu, e, 4);

            v -= invS * (ps + pc);
            if (j == 0) v += ent + __logf(e);

            lab = nlab;
            chunk = next;
            srow += chunk_stride;
        }
    } else {
        // ================= guarded fallback (n % 4 != 0) ===================
        while (chunk < nchunks) {
            const int next = chunk + total_warps;

            int nlab = 0;
            if (next < nchunks && lane < 4) {
                int r = next * 4 + lane;
                if (r >= n) r = n - 1;
                nlab = is64 ? (int)((const long long*)labels)[r]
                            : ((const int*)labels)[r];
            }

            float2 lut = make_float2(0.f, 0.f);
            if (lane < 4) lut = g_lut[lab];

            const int   L    = __shfl_sync(0xffffffffu, lab,   g);
            const float invS = __shfl_sync(0xffffffffu, lut.x, g);
            const float ent  = __shfl_sync(0xffffffffu, lut.y, g);

            const int row = chunk * 4 + g;
            const bool valid = (row < n);
            const float4* sv = (const float4*)srow;

            float4 a = make_float4(0.f, 0.f, 0.f, 0.f), b = a, c4 = a, dd = a;
            float s0 = 0.f, s1 = 0.f, s2 = 0.f;
            if (valid) {
                a  = sv[j];
                b  = sv[j + 8];
                c4 = sv[j + 16];
                if (j == 0) dd = sv[24];
                const int c0 = L - 8 + j;
                const int c1 = L + j;
                if (c0 >= 0) s0 = srow[c0];
                if (c1 < C)  s1 = srow[c1];
                if (j == 0 && L + 8 < C) s2 = srow[L + 8];
            }

            float e = 0.f, ps = 0.f;
            if (valid) {
                e  = __expf(a.x) + __expf(a.y) + __expf(a.z) + __expf(a.w)
                   + __expf(b.x) + __expf(b.y) + __expf(b.z) + __expf(b.w)
                   + __expf(c4.x) + __expf(c4.y) + __expf(c4.z) + __expf(c4.w);
                ps = a.x + a.y + a.z + a.w
                   + b.x + b.y + b.z + b.w
                   + c4.x + c4.y + c4.z + c4.w;
                if (j == 0) {
                    e  += __expf(dd.x) + __expf(dd.y) + __expf(dd.z) + __expf(dd.w);
                    ps += dd.x + dd.y + dd.z + dd.w;
                }
            }
            const float pc = w0 * s0 + w1 * s1 + w2 * s2;

            e += __shfl_xor_sync(0xffffffffu, e, 1);
            e += __shfl_xor_sync(0xffffffffu, e, 2);
            e += __shfl_xor_sync(0xffffffffu, e, 4);

            if (valid) {
                v -= invS * (ps + pc);
                if (j == 0) v += ent + __logf(e);
            }

            lab = nlab;
            chunk = next;
            srow += chunk_stride;
        }
    }

    // --- single final per-warp reduce ---
#pragma unroll
    for (int off = 16; off; off >>= 1)
        v += __shfl_xor_sync(0xffffffffu, v, off);

    if (lane == 0)
        atomicAdd(&s_partial, v);
    __syncthreads();

    if (threadIdx.x == 0) {
        atomicAdd(&g_acc, (double)s_partial);
        __threadfence();
        unsigned int done = atomicAdd(&g_count, 1u);
        if (done == (unsigned int)(nblocks - 1)) {
            double total = atomicAdd(&g_acc, 0.0);
            out[0] = (float)(total / (double)n);
        }
    }
}

extern "C" void kernel_launch(void* const* d_in, const int* in_sizes, int n_in,
                              void* d_out, int out_size) {
    const float* scores = (const float*)d_in[0];
    const void*  labels = d_in[1];
    const int n = in_sizes[1];  // number of rows / labels

    prep<<<C, 32>>>((const int*)labels, n);
    kl_main<<<GRID_BLOCKS, 256>>>(scores, labels, (float*)d_out, n, GRID_BLOCKS);
}